// round 13
// baseline (speedup 1.0000x reference)
#include <cuda_runtime.h>
#include <cuda_fp16.h>

#define B    512
#define L    32768
#define WSZ  100                 // WINDOW*3 - 2
#define NOUT (L - WSZ + 1)       // 32669
#define TPB  256
#define KPT  16
#define CHUNK (TPB * KPT)        // 4096 outputs per block
#define NCHUNK 8                 // ceil(NOUT/CHUNK)
#define STAGE (CHUNK + WSZ - 1)  // 4195 staged inputs
#define RGROUPS 8
#define ROWS_PER_G (B / RGROUPS) // 64

// float staging: 4-float pad per 32-group; 4-aligned float4 vectors never
// straddle a pad; 8-lane LDS.128 phases cover all 32 banks (conflict-free).
#define IX4(i)  ((i) + (((i) >> 5) << 2))
#define SPAD    ((IX4(STAGE) + 8 + 3) & ~3)
// half staging: pad 1 per 16
#define IXH(i)  ((i) + ((i) >> 4))
#define HPAD    ((IXH(CHUNK) + 4 + 7) & ~7)

#define TOTAL ((size_t)B * NOUT)

// Scratch (static device arrays)
__device__ __half g_corr_h[TOTAL];
__device__ float  g_partial[RGROUPS * NOUT];
__device__ float  g_avg[NOUT];

// K1: one (row, 4096-col chunk) per block, 256 threads x 16 outputs.
__global__ __launch_bounds__(TPB) void corr_kernel(const float* __restrict__ x) {
    __shared__ __align__(16) float  sa[SPAD];
    __shared__ __align__(16) float  sb[SPAD];
    __shared__ __align__(16) __half rs[HPAD];

    const int row = blockIdx.y;
    const int c0  = blockIdx.x * CHUNK;
    const float* __restrict__ x1 = x + (size_t)row * (2 * L);
    const float* __restrict__ x2 = x1 + L;

    // ---- stage: float4 gmem loads -> float4 shared stores ----
    for (int i4 = threadIdx.x * 4; i4 < STAGE; i4 += TPB * 4) {
        int idx = c0 + i4;
        if (i4 + 3 < STAGE && idx + 3 < L) {
            *reinterpret_cast<float4*>(sa + IX4(i4)) = *reinterpret_cast<const float4*>(x1 + idx);
            *reinterpret_cast<float4*>(sb + IX4(i4)) = *reinterpret_cast<const float4*>(x2 + idx);
        } else {
            #pragma unroll
            for (int e = 0; e < 4; e++) {
                int i = i4 + e;
                if (i < STAGE) {
                    int id = c0 + i;
                    float a = 0.f, b = 0.f;
                    if (id < L) { a = x1[id]; b = x2[id]; }
                    sa[IX4(i)] = a; sb[IX4(i)] = b;
                }
            }
        }
    }
    __syncthreads();

    const int base = threadIdx.x * KPT;

    // ---- initial 100-tap window: 25 float4 loads per array ----
    float s1 = 0.f, s2 = 0.f, s11 = 0.f, s22 = 0.f, s12 = 0.f;
    #pragma unroll
    for (int m = 0; m < WSZ / 4; m++) {
        float4 a4 = *reinterpret_cast<const float4*>(sa + IX4(base + 4 * m));
        float4 b4 = *reinterpret_cast<const float4*>(sb + IX4(base + 4 * m));
        s1  += a4.x + a4.y + a4.z + a4.w;
        s2  += b4.x + b4.y + b4.z + b4.w;
        s11 += a4.x * a4.x + a4.y * a4.y + a4.z * a4.z + a4.w * a4.w;
        s22 += b4.x * b4.x + b4.y * b4.y + b4.z * b4.z + b4.w * b4.w;
        s12 += a4.x * b4.x + a4.y * b4.y + a4.z * b4.z + a4.w * b4.w;
    }

    // ---- slide + emit, 4 macro-steps of 4 outputs ----
    const float invw = 1.0f / (float)WSZ;
    #pragma unroll
    for (int q = 0; q < KPT / 4; q++) {
        const int k0 = 4 * q;
        float4 oa = *reinterpret_cast<const float4*>(sa + IX4(base + k0));
        float4 ob = *reinterpret_cast<const float4*>(sb + IX4(base + k0));
        float4 na = *reinterpret_cast<const float4*>(sa + IX4(base + WSZ + k0));
        float4 nb = *reinterpret_cast<const float4*>(sb + IX4(base + WSZ + k0));

        float oav[4] = {oa.x, oa.y, oa.z, oa.w};
        float obv[4] = {ob.x, ob.y, ob.z, ob.w};
        float nav[4] = {na.x, na.y, na.z, na.w};
        float nbv[4] = {nb.x, nb.y, nb.z, nb.w};

        #pragma unroll
        for (int e = 0; e < 4; e++) {
            float cov = s12 - s1 * s2 * invw;
            float v1  = s11 - s1 * s1 * invw;
            float v2  = s22 - s2 * s2 * invw;
            rs[IXH(base + k0 + e)] = __float2half_rn(cov * rsqrtf(v1 * v2));
            float an = nav[e], bn = nbv[e], ao = oav[e], bo = obv[e];
            s1  += an - ao;
            s2  += bn - bo;
            s11 += an * an - ao * ao;
            s22 += bn * bn - bo * bo;
            s12 += an * bn - ao * bo;
        }
    }
    __syncthreads();

    // ---- coalesced half store ----
    __half* __restrict__ orow = g_corr_h + (size_t)row * NOUT;
    for (int i = threadIdx.x; i < CHUNK; i += TPB) {
        int j = c0 + i;
        if (j < NOUT) orow[j] = rs[IXH(i)];
    }
}

// K2: partial column sums over 64-row groups (coalesced scalar half reads).
__global__ __launch_bounds__(256) void colsum_kernel() {
    int c = blockIdx.x * blockDim.x + threadIdx.x;
    int g = blockIdx.y;
    if (c >= NOUT) return;
    const __half* __restrict__ p = g_corr_h + (size_t)g * ROWS_PER_G * NOUT + c;
    float s = 0.f;
    #pragma unroll
    for (int r = 0; r < ROWS_PER_G; r++) s += __half2float(p[(size_t)r * NOUT]);
    g_partial[g * NOUT + c] = s;
}

// K2b: collapse partials -> avg.
__global__ __launch_bounds__(256) void avg_kernel() {
    int c = blockIdx.x * blockDim.x + threadIdx.x;
    if (c >= NOUT) return;
    float s = 0.f;
    #pragma unroll
    for (int g = 0; g < RGROUPS; g++) s += g_partial[g * NOUT + c];
    g_avg[c] = s * (1.0f / (float)B);
}

// K3: out = relu(corr - avg). 8 elems/thread, STRIDED by blockDim so every
// load/store instruction is lane-consecutive (1 line per instr for avg/out).
#define FEPT 8
#define FBLK (256 * FEPT)   // 2048 elems per block
__global__ __launch_bounds__(256) void final_kernel(float* __restrict__ out) {
    size_t blockStart = (size_t)blockIdx.x * FBLK;
    size_t i0 = blockStart + threadIdx.x;
    int c = (int)(i0 % NOUT);
    #pragma unroll
    for (int e = 0; e < FEPT; e++) {
        size_t idx = i0 + (size_t)e * 256;
        if (idx < TOTAL) {
            float v = __half2float(g_corr_h[idx]);
            float r = v - g_avg[c];
            out[idx] = r > 0.f ? r : 0.f;
        }
        c += 256;
        if (c >= NOUT) c -= NOUT;
    }
}

extern "C" void kernel_launch(void* const* d_in, const int* in_sizes, int n_in,
                              void* d_out, int out_size) {
    const float* x = (const float*)d_in[0];
    float* out = (float*)d_out;

    dim3 g1(NCHUNK, B);
    corr_kernel<<<g1, TPB>>>(x);

    dim3 g2((NOUT + 255) / 256, RGROUPS);
    colsum_kernel<<<g2, 256>>>();

    avg_kernel<<<(NOUT + 255) / 256, 256>>>();

    unsigned fgrid = (unsigned)((TOTAL + FBLK - 1) / FBLK);
    final_kernel<<<fgrid, 256>>>(out);
}

// round 14
// speedup vs baseline: 1.1729x; 1.1729x over previous
#include <cuda_runtime.h>
#include <cuda_fp16.h>

#define B    512
#define L    32768
#define WSZ  100                 // WINDOW*3 - 2
#define NOUT (L - WSZ + 1)       // 32669
#define TPB  128
#define KPT  32
#define CHUNK (TPB * KPT)        // 4096 outputs per block
#define NCHUNK 8                 // ceil(NOUT/CHUNK)
#define STAGE (CHUNK + WSZ)      // 4196 pairs (1 extra: dead last slide reads pair 4195)
#define RGROUPS 8
#define ROWS_PER_G (B / RGROUPS) // 64

// pair staging: pad 2 pairs per 32. Lane stride 32 pairs -> word stride 68 ->
// start banks 4t: distinct within every 8-lane LDS.128 phase. Pads at 32-pair
// boundaries; all float4 accesses use even pair index within one 32-block.
#define IXP(i)  ((i) + (((i) >> 5) << 1))
#define PALLOC  (((IXP(STAGE) + 7) / 4) * 4)    // float2 count, 16B-aligned region

#define NBLK   260                // block sums of 16 pairs; max needed = 2*127+5 = 259
// half result staging: pad 1 per 16 -> byte stride 68 -> word 17t (conflict-free)
#define IXH(i)  ((i) + ((i) >> 4))
#define HALLOC  (IXH(CHUNK) + 8)

#define UNION_BYTES 8720          // max(rs: HALLOC*2 = 8720, blocksums: 5*NBLK*4 = 5200)

#define TOTAL ((size_t)B * NOUT)

// Scratch (static device arrays)
__device__ __half g_corr_h[TOTAL];
__device__ float  g_partial[RGROUPS * NOUT];
__device__ float  g_avg[NOUT];

// K1: one (row, 4096-col chunk) per block. Interleaved (a,b) pairs, 16-pair
// block sums for the initial window, exact sliding thereafter.
__global__ __launch_bounds__(TPB) void corr_kernel(const float* __restrict__ x) {
    __shared__ __align__(16) float2 sp[PALLOC];
    __shared__ __align__(16) unsigned char uni[UNION_BYTES];

    float* bs1  = (float*)uni;            // [NBLK]
    float* bs2  = bs1  + NBLK;
    float* bs11 = bs2  + NBLK;
    float* bs22 = bs11 + NBLK;
    float* bs12 = bs22 + NBLK;

    const int row = blockIdx.y;
    const int c0  = blockIdx.x * CHUNK;
    const float* __restrict__ x1 = x + (size_t)row * (2 * L);
    const float* __restrict__ x2 = x1 + L;

    // ---- stage interleaved pairs: 2x LDG.128 -> 2x STS.128 per 4 pairs ----
    for (int i4 = threadIdx.x * 4; i4 < STAGE; i4 += TPB * 4) {
        int idx = c0 + i4;
        if (i4 + 3 < STAGE && idx + 3 < L) {
            float4 va = *reinterpret_cast<const float4*>(x1 + idx);
            float4 vb = *reinterpret_cast<const float4*>(x2 + idx);
            *reinterpret_cast<float4*>(sp + IXP(i4))     = make_float4(va.x, vb.x, va.y, vb.y);
            *reinterpret_cast<float4*>(sp + IXP(i4 + 2)) = make_float4(va.z, vb.z, va.w, vb.w);
        } else {
            #pragma unroll
            for (int e = 0; e < 4; e++) {
                int i = i4 + e;
                if (i < STAGE) {
                    int id = c0 + i;
                    float a = 0.f, b = 0.f;
                    if (id < L) { a = x1[id]; b = x2[id]; }
                    sp[IXP(i)] = make_float2(a, b);
                }
            }
        }
    }
    __syncthreads();

    // ---- block sums (16 pairs each), shared across threads ----
    for (int b = threadIdx.x; b < NBLK; b += TPB) {
        float t1 = 0.f, t2 = 0.f, t11 = 0.f, t22 = 0.f, t12 = 0.f;
        #pragma unroll
        for (int e = 0; e < 16; e += 2) {
            float4 p = *reinterpret_cast<const float4*>(sp + IXP(16 * b + e));
            t1  += p.x + p.z;
            t2  += p.y + p.w;
            t11 += p.x * p.x + p.z * p.z;
            t22 += p.y * p.y + p.w * p.w;
            t12 += p.x * p.y + p.z * p.w;
        }
        bs1[b] = t1; bs2[b] = t2; bs11[b] = t11; bs22[b] = t22; bs12[b] = t12;
    }
    __syncthreads();

    // ---- init window = 6 block sums + 4 edge pairs ----
    const int base = threadIdx.x * KPT;      // 16-aligned pair index
    const int b0   = threadIdx.x * 2;        // base / 16
    float s1 = 0.f, s2 = 0.f, s11 = 0.f, s22 = 0.f, s12 = 0.f;
    #pragma unroll
    for (int j = 0; j < 6; j++) {
        s1 += bs1[b0 + j]; s2 += bs2[b0 + j];
        s11 += bs11[b0 + j]; s22 += bs22[b0 + j]; s12 += bs12[b0 + j];
    }
    #pragma unroll
    for (int e = 96; e < 100; e += 2) {
        float4 p = *reinterpret_cast<const float4*>(sp + IXP(base + e));
        s1  += p.x + p.z;
        s2  += p.y + p.w;
        s11 += p.x * p.x + p.z * p.z;
        s22 += p.y * p.y + p.w * p.w;
        s12 += p.x * p.y + p.z * p.w;
    }
    __syncthreads();   // blocksums fully consumed -> union becomes rs

    __half* rs = (__half*)uni;

    // ---- slide + emit, 2 outputs per macro-step ----
    const float invw = 1.0f / (float)WSZ;
    #pragma unroll
    for (int q = 0; q < KPT / 2; q++) {
        const int k = 2 * q;
        float4 op = *reinterpret_cast<const float4*>(sp + IXP(base + k));         // pairs k, k+1
        float4 np = *reinterpret_cast<const float4*>(sp + IXP(base + WSZ + k));   // pairs k+100, k+101

        // output k
        {
            float cov = fmaf(s1 * s2, -invw, s12);
            float v1  = fmaf(s1 * s1, -invw, s11);
            float v2  = fmaf(s2 * s2, -invw, s22);
            rs[IXH(base + k)] = __float2half_rn(cov * rsqrtf(v1 * v2));
        }
        s1 += np.x - op.x;
        s2 += np.y - op.y;
        s11 = fmaf(np.x, np.x, fmaf(-op.x, op.x, s11));
        s22 = fmaf(np.y, np.y, fmaf(-op.y, op.y, s22));
        s12 = fmaf(np.x, np.y, fmaf(-op.x, op.y, s12));

        // output k+1
        {
            float cov = fmaf(s1 * s2, -invw, s12);
            float v1  = fmaf(s1 * s1, -invw, s11);
            float v2  = fmaf(s2 * s2, -invw, s22);
            rs[IXH(base + k + 1)] = __float2half_rn(cov * rsqrtf(v1 * v2));
        }
        s1 += np.z - op.z;
        s2 += np.w - op.w;
        s11 = fmaf(np.z, np.z, fmaf(-op.z, op.z, s11));
        s22 = fmaf(np.w, np.w, fmaf(-op.w, op.w, s22));
        s12 = fmaf(np.z, np.w, fmaf(-op.z, op.w, s12));
    }
    __syncthreads();

    // ---- coalesced half store ----
    __half* __restrict__ orow = g_corr_h + (size_t)row * NOUT;
    for (int i = threadIdx.x; i < CHUNK; i += TPB) {
        int j = c0 + i;
        if (j < NOUT) orow[j] = rs[IXH(i)];
    }
}

// K2: partial column sums over 64-row groups (coalesced scalar half reads).
__global__ __launch_bounds__(256) void colsum_kernel() {
    int c = blockIdx.x * blockDim.x + threadIdx.x;
    int g = blockIdx.y;
    if (c >= NOUT) return;
    const __half* __restrict__ p = g_corr_h + (size_t)g * ROWS_PER_G * NOUT + c;
    float s = 0.f;
    #pragma unroll
    for (int r = 0; r < ROWS_PER_G; r++) s += __half2float(p[(size_t)r * NOUT]);
    g_partial[g * NOUT + c] = s;
}

// K2b: collapse partials -> avg.
__global__ __launch_bounds__(256) void avg_kernel() {
    int c = blockIdx.x * blockDim.x + threadIdx.x;
    if (c >= NOUT) return;
    float s = 0.f;
    #pragma unroll
    for (int g = 0; g < RGROUPS; g++) s += g_partial[g * NOUT + c];
    g_avg[c] = s * (1.0f / (float)B);
}

// K3: out = relu(corr - avg). Column-block x 8 rows: avg loaded once per
// thread and reused; all corr/out accesses lane-consecutive.
#define FR 8
__global__ __launch_bounds__(256) void final_kernel(float* __restrict__ out) {
    int c = blockIdx.x * 256 + threadIdx.x;
    if (c >= NOUT) return;
    float a = g_avg[c];
    size_t ro = (size_t)blockIdx.y * FR * NOUT + c;
    #pragma unroll
    for (int r = 0; r < FR; r++) {
        float v = __half2float(g_corr_h[ro]) - a;
        out[ro] = v > 0.f ? v : 0.f;
        ro += NOUT;
    }
}

extern "C" void kernel_launch(void* const* d_in, const int* in_sizes, int n_in,
                              void* d_out, int out_size) {
    const float* x = (const float*)d_in[0];
    float* out = (float*)d_out;

    dim3 g1(NCHUNK, B);
    corr_kernel<<<g1, TPB>>>(x);

    dim3 g2((NOUT + 255) / 256, RGROUPS);
    colsum_kernel<<<g2, 256>>>();

    avg_kernel<<<(NOUT + 255) / 256, 256>>>();

    dim3 g3((NOUT + 255) / 256, B / FR);
    final_kernel<<<g3, 256>>>(out);
}

// round 16
// speedup vs baseline: 1.3787x; 1.1755x over previous
#include <cuda_runtime.h>
#include <cuda_fp16.h>

#define B    512
#define L    32768
#define WSZ  100                 // WINDOW*3 - 2
#define NOUT (L - WSZ + 1)       // 32669
#define NOUT_P 32672             // padded to multiple of 32 halves (64B rows)
#define TPB  128
#define KPT  32
#define CHUNK (TPB * KPT)        // 4096 outputs per block
#define NCHUNK 8
#define STAGE (CHUNK + WSZ)      // 4196 pairs (1 extra: dead last slide)
#define RGROUPS 8
#define ROWS_PER_G (B / RGROUPS) // 64

typedef unsigned int u32;

// pair staging: pad 2 pairs per 32. All stride-32-pair float4 accesses hit
// distinct banks within each 8-lane LDS.128 phase; vectors never straddle pads.
#define IXP(i)  ((i) + (((i) >> 5) << 1))
#define PALLOC  ((IXP(STAGE) + 3) & ~3)   // float2 count, 16B-aligned size

#define NBLK 130   // 32-pair block sums; init needs blocks t..t+2, t<=127

#define TOTAL ((size_t)B * NOUT)

// Scratch (static device arrays)
__device__ __half g_corr_h[(size_t)B * NOUT_P];
__device__ float  g_partial[RGROUPS * NOUT];
__device__ float  g_avg[NOUT];

// K1: one (row, 4096-col chunk) per block. Interleaved (a,b) pairs, 32-pair
// block sums for window init, exact sliding, direct packed STG.128 output.
__global__ __launch_bounds__(TPB, 6) void corr_kernel(const float* __restrict__ x) {
    __shared__ __align__(16) float2 sp[PALLOC];
    __shared__ float bs1[NBLK], bs2[NBLK], bs11[NBLK], bs22[NBLK], bs12[NBLK];

    const int row = blockIdx.y;
    const int c0  = blockIdx.x * CHUNK;
    const float* __restrict__ x1 = x + (size_t)row * (2 * L);
    const float* __restrict__ x2 = x1 + L;

    // ---- stage interleaved pairs ----
    for (int i4 = threadIdx.x * 4; i4 < STAGE; i4 += TPB * 4) {
        int idx = c0 + i4;
        if (i4 + 3 < STAGE && idx + 3 < L) {
            float4 va = *reinterpret_cast<const float4*>(x1 + idx);
            float4 vb = *reinterpret_cast<const float4*>(x2 + idx);
            *reinterpret_cast<float4*>(sp + IXP(i4))     = make_float4(va.x, vb.x, va.y, vb.y);
            *reinterpret_cast<float4*>(sp + IXP(i4 + 2)) = make_float4(va.z, vb.z, va.w, vb.w);
        } else {
            #pragma unroll
            for (int e = 0; e < 4; e++) {
                int i = i4 + e;
                if (i < STAGE) {
                    int id = c0 + i;
                    float a = 0.f, b = 0.f;
                    if (id < L) { a = x1[id]; b = x2[id]; }
                    sp[IXP(i)] = make_float2(a, b);
                }
            }
        }
    }
    __syncthreads();

    // ---- 32-pair block sums ----
    for (int b = threadIdx.x; b < NBLK; b += TPB) {
        float t1 = 0.f, t2 = 0.f, t11 = 0.f, t22 = 0.f, t12 = 0.f;
        #pragma unroll
        for (int e = 0; e < 32; e += 2) {
            float4 p = *reinterpret_cast<const float4*>(sp + IXP(32 * b + e));
            t1  += p.x + p.z;
            t2  += p.y + p.w;
            t11 += p.x * p.x + p.z * p.z;
            t22 += p.y * p.y + p.w * p.w;
            t12 += p.x * p.y + p.z * p.w;
        }
        bs1[b] = t1; bs2[b] = t2; bs11[b] = t11; bs22[b] = t22; bs12[b] = t12;
    }
    __syncthreads();

    // ---- init window = 3 block sums + 4 edge pairs ----
    const int base = threadIdx.x * KPT;   // 32-aligned pair index
    const int b0   = threadIdx.x;
    float s1 = 0.f, s2 = 0.f, s11 = 0.f, s22 = 0.f, s12 = 0.f;
    #pragma unroll
    for (int j = 0; j < 3; j++) {
        s1 += bs1[b0 + j]; s2 += bs2[b0 + j];
        s11 += bs11[b0 + j]; s22 += bs22[b0 + j]; s12 += bs12[b0 + j];
    }
    #pragma unroll
    for (int e = 96; e < 100; e += 2) {
        float4 p = *reinterpret_cast<const float4*>(sp + IXP(base + e));
        s1  += p.x + p.z;
        s2  += p.y + p.w;
        s11 += p.x * p.x + p.z * p.z;
        s22 += p.y * p.y + p.w * p.w;
        s12 += p.x * p.y + p.z * p.w;
    }

    // ---- slide + emit; pack 8 halves -> STG.128 (no shared round-trip) ----
    const float invw = 1.0f / (float)WSZ;
    const int gcol = c0 + base;                  // multiple of 32
    const bool ok = gcol < NOUT_P;               // last-chunk overflow threads skip stores
    __half* __restrict__ orow = g_corr_h + (size_t)row * NOUT_P + gcol;

    u32 pk[4];
    #pragma unroll
    for (int q = 0; q < KPT / 2; q++) {
        const int k = 2 * q;
        float4 op = *reinterpret_cast<const float4*>(sp + IXP(base + k));
        float4 np = *reinterpret_cast<const float4*>(sp + IXP(base + WSZ + k));

        float r0, r1;
        {
            float cov = fmaf(s1 * s2, -invw, s12);
            float v1  = fmaf(s1 * s1, -invw, s11);
            float v2  = fmaf(s2 * s2, -invw, s22);
            r0 = cov * rsqrtf(v1 * v2);
        }
        s1 += np.x - op.x;
        s2 += np.y - op.y;
        s11 = fmaf(np.x, np.x, fmaf(-op.x, op.x, s11));
        s22 = fmaf(np.y, np.y, fmaf(-op.y, op.y, s22));
        s12 = fmaf(np.x, np.y, fmaf(-op.x, op.y, s12));
        {
            float cov = fmaf(s1 * s2, -invw, s12);
            float v1  = fmaf(s1 * s1, -invw, s11);
            float v2  = fmaf(s2 * s2, -invw, s22);
            r1 = cov * rsqrtf(v1 * v2);
        }
        s1 += np.z - op.z;
        s2 += np.w - op.w;
        s11 = fmaf(np.z, np.z, fmaf(-op.z, op.z, s11));
        s22 = fmaf(np.w, np.w, fmaf(-op.w, op.w, s22));
        s12 = fmaf(np.z, np.w, fmaf(-op.z, op.w, s12));

        __half2 h2 = __halves2half2(__float2half_rn(r0), __float2half_rn(r1));
        pk[q & 3] = *reinterpret_cast<u32*>(&h2);
        if ((q & 3) == 3 && ok) {
            *reinterpret_cast<uint4*>(orow + 8 * (q >> 2)) =
                make_uint4(pk[0], pk[1], pk[2], pk[3]);
        }
    }
}

// K2: partial column sums over 64-row groups; half2 (rows share parity with
// padded stride), 2 columns per thread.
__global__ __launch_bounds__(256) void colsum_kernel() {
    int c = 2 * (blockIdx.x * blockDim.x + threadIdx.x);
    int g = blockIdx.y;
    if (c >= NOUT) return;
    const __half* __restrict__ p = g_corr_h + (size_t)g * ROWS_PER_G * NOUT_P + c;
    float sx = 0.f, sy = 0.f;
    #pragma unroll
    for (int r = 0; r < ROWS_PER_G; r++) {
        __half2 h = *reinterpret_cast<const __half2*>(p + (size_t)r * NOUT_P);
        float2 f = __half22float2(h);
        sx += f.x; sy += f.y;
    }
    g_partial[g * NOUT + c] = sx;
    if (c + 1 < NOUT) g_partial[g * NOUT + c + 1] = sy;
}

// K2b: collapse partials -> avg.
__global__ __launch_bounds__(256) void avg_kernel() {
    int c = blockIdx.x * blockDim.x + threadIdx.x;
    if (c >= NOUT) return;
    float s = 0.f;
    #pragma unroll
    for (int g = 0; g < RGROUPS; g++) s += g_partial[g * NOUT + c];
    g_avg[c] = s * (1.0f / (float)B);
}

// K3: out = relu(corr - avg). Column x 8 rows; avg loaded once per thread.
#define FR 8
__global__ __launch_bounds__(256) void final_kernel(float* __restrict__ out) {
    int c = blockIdx.x * 256 + threadIdx.x;
    if (c >= NOUT) return;
    float a = g_avg[c];
    size_t rc = (size_t)blockIdx.y * FR * NOUT_P + c;
    size_t ro = (size_t)blockIdx.y * FR * NOUT + c;
    #pragma unroll
    for (int r = 0; r < FR; r++) {
        float v = __half2float(g_corr_h[rc]) - a;
        out[ro] = v > 0.f ? v : 0.f;
        rc += NOUT_P;
        ro += NOUT;
    }
}

extern "C" void kernel_launch(void* const* d_in, const int* in_sizes, int n_in,
                              void* d_out, int out_size) {
    const float* x = (const float*)d_in[0];
    float* out = (float*)d_out;

    dim3 g1(NCHUNK, B);
    corr_kernel<<<g1, TPB>>>(x);

    dim3 g2(((NOUT + 1) / 2 + 255) / 256, RGROUPS);
    colsum_kernel<<<g2, 256>>>();

    avg_kernel<<<(NOUT + 255) / 256, 256>>>();

    dim3 g3((NOUT + 255) / 256, B / FR);
    final_kernel<<<g3, 256>>>(out);
}